// round 3
// baseline (speedup 1.0000x reference)
#include <cuda_runtime.h>
#include <math.h>

#define NPART 1024
#define MAX_M 262144   // (128/2)^3 upper bound on downsampled voxels

// ---------------- scratch (device globals: allocation-free) ----------------
__device__ float g_hd[(size_t)MAX_M * 128];   // pooled silu(gn(x)) (sum -> mean)
__device__ float g_xd[(size_t)MAX_M * 128];   // pooled x          (sum -> mean)
__device__ float g_cnt[MAX_M];                // per-segment counts
__device__ float g_h1[(size_t)MAX_M * 256];   // conv1 output
__device__ float g_h2[(size_t)MAX_M * 256];   // silu(gn2(h1))
__device__ float g_part[NPART * 64];          // GN partial sums (32 sum + 32 sumsq)
__device__ float g_stats1[64];                // GN1: mu[32], rstd[32]
__device__ float g_stats2[64];                // GN2: mu[32], rstd[32]

// ---------------- f32x2 packed-FMA helpers (2x fp32 throughput) ----------------
__device__ __forceinline__ unsigned long long pk2(float x, float y) {
    unsigned long long r;
    asm("mov.b64 %0, {%1, %2};" : "=l"(r) : "f"(x), "f"(y));
    return r;
}
__device__ __forceinline__ void fma2(unsigned long long& c,
                                     unsigned long long a, unsigned long long b) {
    asm("fma.rn.f32x2 %0, %1, %2, %0;" : "+l"(c) : "l"(a), "l"(b));
}
__device__ __forceinline__ float2 upk2(unsigned long long v) {
    float2 r;
    asm("mov.b64 {%0, %1}, %2;" : "=f"(r.x), "=f"(r.y) : "l"(v));
    return r;
}

// ---------------- misc small kernels ----------------
__global__ void k_zero(int M) {
    int i = blockIdx.x * 256 + threadIdx.x;
    if (i < M * 128) { g_hd[i] = 0.f; g_xd[i] = 0.f; }
    if (i < M) g_cnt[i] = 0.f;
}

// Stage-1 GroupNorm stats: per-block partial (sum, sumsq) per group.
template <int C, bool FROM_H1>
__global__ void k_gn_partial(const float* __restrict__ Xin, int rows) {
    const float* X = FROM_H1 ? (const float*)g_h1 : Xin;
    const int c = threadIdx.x;          // blockDim.x == C
    float s = 0.f, q = 0.f;
    for (int r = blockIdx.x; r < rows; r += NPART) {
        float v = X[(size_t)r * C + c];
        s += v; q += v * v;
    }
    __shared__ float ss[C];
    __shared__ float qq[C];
    ss[c] = s; qq[c] = q;
    __syncthreads();
    if (c < 32) {
        const int cpg = C / 32;
        float S = 0.f, Q = 0.f;
#pragma unroll
        for (int j = 0; j < cpg; ++j) { S += ss[c * cpg + j]; Q += qq[c * cpg + j]; }
        g_part[blockIdx.x * 64 + c]      = S;
        g_part[blockIdx.x * 64 + 32 + c] = Q;
    }
}

__global__ void k_gn_reduce(float inv_n, int which) {
    int t = threadIdx.x;                // 64 threads
    float s = 0.f;
    for (int i = 0; i < NPART; ++i) s += g_part[i * 64 + t];
    __shared__ float sm[64];
    sm[t] = s;
    __syncthreads();
    if (t < 32) {
        float mu  = sm[t] * inv_n;
        float var = sm[32 + t] * inv_n - mu * mu;
        float* st = which ? g_stats2 : g_stats1;
        st[t]      = mu;
        st[32 + t] = rsqrtf(var + 1e-5f);
    }
}

// h = silu(gn1(x)); scatter-add h and x into segment accumulators + counts.
__global__ void k_act_pool(const float* __restrict__ feats,
                           const float* __restrict__ w,
                           const float* __restrict__ b,
                           const int* __restrict__ seg) {
    int i = blockIdx.x;
    int c = threadIdx.x;                // 128
    float x = feats[(size_t)i * 128 + c];
    int g = c >> 2;
    float h = (x - g_stats1[g]) * g_stats1[32 + g] * w[c] + b[c];
    h = h / (1.f + expf(-h));
    int sgm = seg[i];
    atomicAdd(&g_hd[(size_t)sgm * 128 + c], h);
    atomicAdd(&g_xd[(size_t)sgm * 128 + c], x);
    if (c == 0) atomicAdd(&g_cnt[sgm], 1.f);
}

__global__ void k_finalize(int M) {
    int idx = blockIdx.x * 256 + threadIdx.x;
    if (idx >= M * 128) return;
    float inv = 1.f / fmaxf(g_cnt[idx >> 7], 1.f);
    g_hd[idx] *= inv;
    g_xd[idx] *= inv;
}

// h2 = silu(gn2(h1))
__global__ void k_act2(const float* __restrict__ w, const float* __restrict__ b, int M) {
    int idx = blockIdx.x * 256 + threadIdx.x;
    if (idx >= M * 256) return;
    int c = idx & 255, g = c >> 3;
    float v = g_h1[idx];
    float h = (v - g_stats2[g]) * g_stats2[32 + g] * w[c] + b[c];
    g_h2[idx] = h / (1.f + expf(-h));
}

// ---------------- 27-tap gather GEMM (the hot path) ----------------
// Block tile: 64 rows x 64 cols, BK=32, 256 threads, each thread 4x4 via f32x2 pairs.
// As is k-major [kk][row] so row-pairs load as a single LDS.64 -> packed operand.
__device__ __forceinline__ void tile_acc(const float* __restrict__ X, int cin,
                                         const float* __restrict__ Wt,   // already + bn0
                                         const int* __restrict__ ridx,
                                         unsigned long long (&acc)[2][4],
                                         float (*As)[66], float (*Bs)[68],
                                         int tid, int tx, int ty) {
    const int nkc = cin >> 5;
    for (int kc = 0; kc < nkc; ++kc) {
        // load A: 64 gathered rows x 32 channels (512 float4, 2 per thread)
#pragma unroll
        for (int j = 0; j < 2; ++j) {
            int L = (tid << 1) + j;
            int r = L >> 3, f = L & 7;
            int gi = ridx[r];
            float4 v = make_float4(0.f, 0.f, 0.f, 0.f);
            if (gi >= 0)
                v = *(const float4*)(X + (size_t)gi * cin + (kc << 5) + (f << 2));
            int kb = f << 2;
            As[kb + 0][r] = v.x; As[kb + 1][r] = v.y;
            As[kb + 2][r] = v.z; As[kb + 3][r] = v.w;
        }
        // load B: 32 x 64 weight tile (rows stride 256)
#pragma unroll
        for (int j = 0; j < 2; ++j) {
            int L = (tid << 1) + j;
            int kk = L >> 4, f = L & 15;
            float4 v = *(const float4*)(Wt + (size_t)((kc << 5) + kk) * 256 + (f << 2));
            *(float4*)&Bs[kk][f << 2] = v;
        }
        __syncthreads();
#pragma unroll
        for (int kk = 0; kk < 32; ++kk) {
            unsigned long long a01 = *(const unsigned long long*)&As[kk][(ty << 2)];
            unsigned long long a23 = *(const unsigned long long*)&As[kk][(ty << 2) + 2];
            float4 b = *(const float4*)&Bs[kk][tx << 2];
            unsigned long long bx = pk2(b.x, b.x), by = pk2(b.y, b.y);
            unsigned long long bz = pk2(b.z, b.z), bw = pk2(b.w, b.w);
            fma2(acc[0][0], a01, bx); fma2(acc[0][1], a01, by);
            fma2(acc[0][2], a01, bz); fma2(acc[0][3], a01, bw);
            fma2(acc[1][0], a23, bx); fma2(acc[1][1], a23, by);
            fma2(acc[1][2], a23, bz); fma2(acc[1][3], a23, bw);
        }
        __syncthreads();
    }
}

template <int CIN, bool SECOND>
__global__ __launch_bounds__(256) void k_conv(const int* __restrict__ nbr,
                                              const float* __restrict__ W,
                                              const float* __restrict__ bias,
                                              const float* __restrict__ Wsk,
                                              const float* __restrict__ bsk,
                                              float* __restrict__ out_arg, int M) {
    __shared__ float As[32][66];
    __shared__ float Bs[32][68];
    __shared__ int ridx[64];
    const float* X = SECOND ? (const float*)g_h2 : (const float*)g_hd;
    float* out = SECOND ? out_arg : (float*)g_h1;
    const int tid = threadIdx.x, tx = tid & 15, ty = tid >> 4;
    const int bm0 = blockIdx.x << 6, bn0 = blockIdx.y << 6;

    unsigned long long acc[2][4];
#pragma unroll
    for (int i = 0; i < 2; ++i)
#pragma unroll
        for (int j = 0; j < 4; ++j) acc[i][j] = 0ull;

    for (int k = 0; k < 27; ++k) {
        if (tid < 64) {
            int r = bm0 + tid;
            ridx[tid] = (r < M) ? nbr[r * 27 + k] : -1;
        }
        __syncthreads();
        tile_acc(X, CIN, W + (size_t)k * CIN * 256 + bn0, ridx, acc, As, Bs, tid, tx, ty);
    }
    if (SECOND) {   // fused skip: x_d @ Wskip as an identity 28th tap
        if (tid < 64) {
            int r = bm0 + tid;
            ridx[tid] = (r < M) ? r : -1;
        }
        __syncthreads();
        tile_acc((const float*)g_xd, 128, Wsk + bn0, ridx, acc, As, Bs, tid, tx, ty);
    }

    float bv[4];
#pragma unroll
    for (int j = 0; j < 4; ++j) {
        int col = bn0 + (tx << 2) + j;
        bv[j] = bias[col] + (SECOND ? bsk[col] : 0.f);
    }
#pragma unroll
    for (int ip = 0; ip < 2; ++ip) {
        float2 c0 = upk2(acc[ip][0]), c1 = upk2(acc[ip][1]);
        float2 c2 = upk2(acc[ip][2]), c3 = upk2(acc[ip][3]);
        int r0 = bm0 + (ty << 2) + (ip << 1);
        if (r0 < M) {
            float4 o = make_float4(c0.x + bv[0], c1.x + bv[1], c2.x + bv[2], c3.x + bv[3]);
            *(float4*)(out + (size_t)r0 * 256 + bn0 + (tx << 2)) = o;
        }
        if (r0 + 1 < M) {
            float4 o = make_float4(c0.y + bv[0], c1.y + bv[1], c2.y + bv[2], c3.y + bv[3]);
            *(float4*)(out + (size_t)(r0 + 1) * 256 + bn0 + (tx << 2)) = o;
        }
    }
}

// ---------------- launch ----------------
extern "C" void kernel_launch(void* const* d_in, const int* in_sizes, int n_in,
                              void* d_out, int out_size) {
    const float* feats = (const float*)d_in[0];
    const float* gn1w  = (const float*)d_in[1];
    const float* gn1b  = (const float*)d_in[2];
    const float* W1    = (const float*)d_in[3];
    const float* b1    = (const float*)d_in[4];
    const float* gn2w  = (const float*)d_in[5];
    const float* gn2b  = (const float*)d_in[6];
    const float* W2    = (const float*)d_in[7];
    const float* b2    = (const float*)d_in[8];
    const float* Wsk   = (const float*)d_in[9];
    const float* bsk   = (const float*)d_in[10];
    const int*   seg   = (const int*)d_in[11];
    const int*   nbr   = (const int*)d_in[12];

    const int N = in_sizes[0] / 128;
    const int M = in_sizes[12] / 27;

    // 1) zero pooling accumulators
    k_zero<<<(M * 128 + 255) / 256, 256>>>(M);
    // 2) GroupNorm-1 global stats (deterministic two-stage)
    k_gn_partial<128, false><<<NPART, 128>>>(feats, N);
    k_gn_reduce<<<1, 64>>>(1.f / (4.f * (float)N), 0);
    // 3) silu(gn1(x)) + segment-sum pooling of h and x (+counts)
    k_act_pool<<<N, 128>>>(feats, gn1w, gn1b, seg);
    // 4) sums -> means
    k_finalize<<<(M * 128 + 255) / 256, 256>>>(M);
    // 5) conv1: h1 = sparseconv27(h_d, W1) + b1
    const int gm = (M + 63) >> 6;
    k_conv<128, false><<<dim3(gm, 4), 256>>>(nbr, W1, b1, nullptr, nullptr, nullptr, M);
    // 6) GroupNorm-2 stats on h1
    k_gn_partial<256, true><<<NPART, 256>>>(nullptr, M);
    k_gn_reduce<<<1, 64>>>(1.f / (8.f * (float)M), 1);
    // 7) h2 = silu(gn2(h1))
    k_act2<<<(M * 256 + 255) / 256, 256>>>(gn2w, gn2b, M);
    // 8) conv2 + fused skip (+b2 +bskip) -> d_out
    k_conv<256, true><<<dim3(gm, 4), 256>>>(nbr, W2, b2, Wsk, bsk, (float*)d_out, M);
}

// round 10
// speedup vs baseline: 2.7589x; 2.7589x over previous
#include <cuda_runtime.h>
#include <cuda_bf16.h>
#include <math.h>
#include <stdint.h>

#define NPART 1024
#define MAX_M 204800   // M <= N = 200000

// ---------------- scratch (device globals: allocation-free) ----------------
__device__ float g_hd[(size_t)MAX_M * 128];   // pooled silu(gn(x)) accumulator
__device__ float g_xd[(size_t)MAX_M * 128];   // pooled x accumulator
__device__ float g_cnt[MAX_M];
__device__ float g_h1[(size_t)MAX_M * 256];   // conv1 output (fp32, for GN2)
__device__ float g_part[NPART * 64];
__device__ float g_stats1[64];
__device__ float g_stats2[64];
// bf16 hi/lo split activations
__device__ __nv_bfloat16 g_hdh[(size_t)MAX_M * 128];
__device__ __nv_bfloat16 g_hdl[(size_t)MAX_M * 128];
__device__ __nv_bfloat16 g_xdh[(size_t)MAX_M * 128];
__device__ __nv_bfloat16 g_xdl[(size_t)MAX_M * 128];
__device__ __nv_bfloat16 g_h2h[(size_t)MAX_M * 256];
__device__ __nv_bfloat16 g_h2l[(size_t)MAX_M * 256];
// split + transposed weights, layout [tap][cout][cin]
__device__ __nv_bfloat16 g_W1h[27 * 256 * 128];
__device__ __nv_bfloat16 g_W1l[27 * 256 * 128];
__device__ __nv_bfloat16 g_W2h[27 * 256 * 256];
__device__ __nv_bfloat16 g_W2l[27 * 256 * 256];
__device__ __nv_bfloat16 g_Wsh[256 * 128];
__device__ __nv_bfloat16 g_Wsl[256 * 128];

// ---------------- PTX helpers (portable sm_80+ paths only) ----------------
__device__ __forceinline__ uint32_t s2u(const void* p) {
    uint32_t a;
    asm("{ .reg .u64 t; cvta.to.shared.u64 t, %1; cvt.u32.u64 %0, t; }" : "=r"(a) : "l"(p));
    return a;
}
__device__ __forceinline__ void cpa(uint32_t dst, const void* src, unsigned sz) {
    asm volatile("cp.async.cg.shared.global [%0], [%1], 16, %2;"
                 :: "r"(dst), "l"(src), "r"(sz) : "memory");
}
__device__ __forceinline__ void cp_commit() {
    asm volatile("cp.async.commit_group;" ::: "memory");
}
__device__ __forceinline__ void cp_wait1() {
    asm volatile("cp.async.wait_group 1;" ::: "memory");
}
__device__ __forceinline__ void ldsm4(uint32_t a, uint32_t* r) {
    asm volatile("ldmatrix.sync.aligned.m8n8.x4.shared.b16 {%0,%1,%2,%3}, [%4];"
                 : "=r"(r[0]), "=r"(r[1]), "=r"(r[2]), "=r"(r[3]) : "r"(a));
}
__device__ __forceinline__ void mma16816(float* d, const uint32_t* a,
                                         uint32_t b0, uint32_t b1) {
    asm volatile(
        "mma.sync.aligned.m16n8k16.row.col.f32.bf16.bf16.f32 "
        "{%0,%1,%2,%3},{%4,%5,%6,%7},{%8,%9},{%0,%1,%2,%3};"
        : "+f"(d[0]), "+f"(d[1]), "+f"(d[2]), "+f"(d[3])
        : "r"(a[0]), "r"(a[1]), "r"(a[2]), "r"(a[3]), "r"(b0), "r"(b1));
}
#define SWZ(x) ((x) ^ (((x) >> 3) & 0x70))

// ---------------- small kernels ----------------
__global__ void k_zero(int M) {
    int i = blockIdx.x * 256 + threadIdx.x;
    if (i < M * 128) { g_hd[i] = 0.f; g_xd[i] = 0.f; }
    if (i < M) g_cnt[i] = 0.f;
}

template <int C, bool FROM_H1>
__global__ void k_gn_partial(const float* __restrict__ Xin, int rows) {
    const float* X = FROM_H1 ? (const float*)g_h1 : Xin;
    const int c = threadIdx.x;
    float s = 0.f, q = 0.f;
    for (int r = blockIdx.x; r < rows; r += NPART) {
        float v = X[(size_t)r * C + c];
        s += v; q += v * v;
    }
    __shared__ float ss[C];
    __shared__ float qq[C];
    ss[c] = s; qq[c] = q;
    __syncthreads();
    if (c < 32) {
        const int cpg = C / 32;
        float S = 0.f, Q = 0.f;
#pragma unroll
        for (int j = 0; j < cpg; ++j) { S += ss[c * cpg + j]; Q += qq[c * cpg + j]; }
        g_part[blockIdx.x * 64 + c]      = S;
        g_part[blockIdx.x * 64 + 32 + c] = Q;
    }
}

__global__ void k_gn_reduce(float inv_n, int which) {
    int t = threadIdx.x;
    float s = 0.f;
    for (int i = 0; i < NPART; ++i) s += g_part[i * 64 + t];
    __shared__ float sm[64];
    sm[t] = s;
    __syncthreads();
    if (t < 32) {
        float mu  = sm[t] * inv_n;
        float var = sm[32 + t] * inv_n - mu * mu;
        float* st = which ? g_stats2 : g_stats1;
        st[t]      = mu;
        st[32 + t] = rsqrtf(var + 1e-5f);
    }
}

__global__ void k_act_pool(const float* __restrict__ feats,
                           const float* __restrict__ w,
                           const float* __restrict__ b,
                           const int* __restrict__ seg) {
    int i = blockIdx.x;
    int c = threadIdx.x;
    float x = feats[(size_t)i * 128 + c];
    int g = c >> 2;
    float h = (x - g_stats1[g]) * g_stats1[32 + g] * w[c] + b[c];
    h = h / (1.f + expf(-h));
    int sgm = seg[i];
    atomicAdd(&g_hd[(size_t)sgm * 128 + c], h);
    atomicAdd(&g_xd[(size_t)sgm * 128 + c], x);
    if (c == 0) atomicAdd(&g_cnt[sgm], 1.f);
}

// means -> bf16 hi/lo splits
__global__ void k_finalize(int M) {
    int idx = blockIdx.x * 256 + threadIdx.x;
    if (idx >= M * 128) return;
    float inv = 1.f / fmaxf(g_cnt[idx >> 7], 1.f);
    float hv = g_hd[idx] * inv;
    float xv = g_xd[idx] * inv;
    __nv_bfloat16 hh = __float2bfloat16(hv);
    __nv_bfloat16 xh = __float2bfloat16(xv);
    g_hdh[idx] = hh; g_hdl[idx] = __float2bfloat16(hv - __bfloat162float(hh));
    g_xdh[idx] = xh; g_xdl[idx] = __float2bfloat16(xv - __bfloat162float(xh));
}

// h2 = silu(gn2(h1)) -> bf16 hi/lo
__global__ void k_act2(const float* __restrict__ w, const float* __restrict__ b, int M) {
    int idx = blockIdx.x * 256 + threadIdx.x;
    if (idx >= M * 256) return;
    int c = idx & 255, g = c >> 3;
    float v = g_h1[idx];
    float h = (v - g_stats2[g]) * g_stats2[32 + g] * w[c] + b[c];
    h = h / (1.f + expf(-h));
    __nv_bfloat16 hh = __float2bfloat16(h);
    g_h2h[idx] = hh;
    g_h2l[idx] = __float2bfloat16(h - __bfloat162float(hh));
}

// W [tap][cin][cout] fp32 -> [tap][cout][cin] bf16 hi/lo
template <int WHICH>
__global__ void k_wsplit(const float* __restrict__ W, int CIN, int COUT, int total) {
    __nv_bfloat16* Oh = WHICH == 0 ? g_W1h : WHICH == 1 ? g_W2h : g_Wsh;
    __nv_bfloat16* Ol = WHICH == 0 ? g_W1l : WHICH == 1 ? g_W2l : g_Wsl;
    int idx = blockIdx.x * 256 + threadIdx.x;
    if (idx >= total) return;
    int ci = idx % CIN;
    int t = idx / CIN;
    int co = t % COUT;
    int k = t / COUT;
    float v = W[((size_t)k * CIN + ci) * COUT + co];
    __nv_bfloat16 h = __float2bfloat16(v);
    Oh[idx] = h;
    Ol[idx] = __float2bfloat16(v - __bfloat162float(h));
}

// ---------------- HMMA 27-tap gather GEMM ----------------
// CTA 128x128, 8 warps (warp = 32m x 64n), BK=64, 2-stage cp.async pipeline,
// bf16 hi/lo 3-pass split (hh + hl + lh), fp32 register accumulators.
#define STG 65536   // Ah 16K | Al 16K | Bh 16K | Bl 16K
#define SMEM_SZ (2 * STG + 1024)

template <bool SECOND>
__global__ void __launch_bounds__(256, 1)
k_conv_mma(const int* __restrict__ nbr, const float* __restrict__ bias,
           const float* __restrict__ bsk, float* __restrict__ out_arg, int M) {
    extern __shared__ char smem[];
    const uint32_t sb = s2u(smem);
    int* ridx = (int*)(smem + 2 * STG);   // [2][128]
    const int tid = threadIdx.x, lane = tid & 31, wid = tid >> 5;
    const int bm0 = blockIdx.x << 7, bn0 = blockIdx.y << 7;
    const int mbase = (wid >> 1) * 32, nbase = (wid & 1) * 64;
    float* out = SECOND ? out_arg : (float*)g_h1;
    const int NC = SECOND ? 110 : 54;
    const int TT = SECOND ? 28 : 27;

    float acc[2][8][4];
#pragma unroll
    for (int i = 0; i < 2; ++i)
#pragma unroll
        for (int j = 0; j < 8; ++j)
#pragma unroll
            for (int q = 0; q < 4; ++q) acc[i][j][q] = 0.f;

    // precomputed ldmatrix lane geometry
    const int lj = lane >> 3, lr = lane & 7;
    int arow[2], brow[4];
#pragma unroll
    for (int mt = 0; mt < 2; ++mt) arow[mt] = mbase + mt * 16 + (lj & 1) * 8 + lr;
#pragma unroll
    for (int p = 0; p < 4; ++p) brow[p] = nbase + p * 16 + (lj >> 1) * 8 + lr;
    const int akb = (lj >> 1) * 16, bkb = (lj & 1) * 16;

    auto issue = [&](int c) {
        int tap, cc, Kd;
        const __nv_bfloat16 *Xh, *Xl, *Wh, *Wl;
        if (SECOND) {
            if (c < 108) {
                tap = c >> 2; cc = c & 3; Kd = 256;
                Xh = g_h2h; Xl = g_h2l;
                size_t wo = ((size_t)tap * 256 + bn0) * 256;
                Wh = g_W2h + wo; Wl = g_W2l + wo;
            } else {
                tap = 27; cc = c - 108; Kd = 128;
                Xh = g_xdh; Xl = g_xdl;
                size_t wo = (size_t)bn0 * 128;
                Wh = g_Wsh + wo; Wl = g_Wsl + wo;
            }
        } else {
            tap = c >> 1; cc = c & 1; Kd = 128;
            Xh = g_hdh; Xl = g_hdl;
            size_t wo = ((size_t)tap * 256 + bn0) * 128;
            Wh = g_W1h + wo; Wl = g_W1l + wo;
        }
        const uint32_t S = sb + (c & 1) * STG;
        const int row = tid >> 1;
        int gi = ridx[(tap & 1) * 128 + row];
        unsigned sz = (gi >= 0) ? 16u : 0u;
        size_t xo = (size_t)(gi >= 0 ? gi : 0) * Kd + cc * 64;
        size_t woff = (size_t)row * Kd + cc * 64;
#pragma unroll
        for (int i = 0; i < 4; ++i) {
            int seg = (tid & 1) * 4 + i;
            uint32_t off = SWZ(row * 128 + seg * 16);
            cpa(S + off,         Xh + xo + seg * 8, sz);
            cpa(S + 16384 + off, Xl + xo + seg * 8, sz);
            cpa(S + 32768 + off, Wh + woff + seg * 8, 16u);
            cpa(S + 49152 + off, Wl + woff + seg * 8, 16u);
        }
    };

    // prologue: ridx for tap 0, issue chunk 0
    if (tid < 128) {
        int r = bm0 + tid;
        ridx[tid] = (r < M) ? nbr[r * 27] : -1;
    }
    __syncthreads();
    issue(0);
    cp_commit();

    for (int c = 0; c < NC; ++c) {
        if (c + 1 < NC) issue(c + 1);
        cp_commit();
        cp_wait1();
        __syncthreads();

        int tap, cc;
        if (SECOND) {
            if (c < 108) { tap = c >> 2; cc = c & 3; }
            else         { tap = 27; cc = c - 108; }
        } else { tap = c >> 1; cc = c & 1; }

        // prefetch ridx for next tap (used >=1 chunk later; visible after
        // this iteration's trailing barrier)
        if (cc == 0 && tap + 1 < TT && tid < 128) {
            int r = bm0 + tid;
            int v;
            if (SECOND && tap + 1 == 27) v = (r < M) ? r : -1;
            else                         v = (r < M) ? nbr[r * 27 + tap + 1] : -1;
            ridx[((tap + 1) & 1) * 128 + tid] = v;
        }

        const uint32_t Sb = sb + (c & 1) * STG;
#pragma unroll
        for (int pass = 0; pass < 3; ++pass) {
            const uint32_t As = Sb + (pass == 2 ? 16384 : 0);
            const uint32_t Bs = Sb + (pass == 1 ? 49152 : 32768);
#pragma unroll
            for (int ks = 0; ks < 4; ++ks) {
                uint32_t a[2][4], b[4][4];
#pragma unroll
                for (int mt = 0; mt < 2; ++mt)
                    ldsm4(As + arow[mt] * 128 +
                          ((ks * 32 + akb) ^ ((arow[mt] & 7) * 16)), a[mt]);
#pragma unroll
                for (int p = 0; p < 4; ++p)
                    ldsm4(Bs + brow[p] * 128 +
                          ((ks * 32 + bkb) ^ ((brow[p] & 7) * 16)), b[p]);
#pragma unroll
                for (int mt = 0; mt < 2; ++mt)
#pragma unroll
                    for (int nt = 0; nt < 8; ++nt)
                        mma16816(acc[mt][nt], a[mt],
                                 b[nt >> 1][(nt & 1) * 2], b[nt >> 1][(nt & 1) * 2 + 1]);
            }
        }
        __syncthreads();
    }

    // epilogue: registers -> gmem with fused bias
#pragma unroll
    for (int nt = 0; nt < 8; ++nt) {
        int col = bn0 + nbase + nt * 8 + (lane & 3) * 2;
        float bx = bias[col]     + (SECOND ? bsk[col]     : 0.f);
        float by = bias[col + 1] + (SECOND ? bsk[col + 1] : 0.f);
#pragma unroll
        for (int mt = 0; mt < 2; ++mt) {
            int r0 = bm0 + mbase + mt * 16 + (lane >> 2);
            if (r0 < M) {
                float2 v = make_float2(acc[mt][nt][0] + bx, acc[mt][nt][1] + by);
                *(float2*)(out + (size_t)r0 * 256 + col) = v;
            }
            int r1 = r0 + 8;
            if (r1 < M) {
                float2 v = make_float2(acc[mt][nt][2] + bx, acc[mt][nt][3] + by);
                *(float2*)(out + (size_t)r1 * 256 + col) = v;
            }
        }
    }
}

// ---------------- launch ----------------
extern "C" void kernel_launch(void* const* d_in, const int* in_sizes, int n_in,
                              void* d_out, int out_size) {
    const float* feats = (const float*)d_in[0];
    const float* gn1w  = (const float*)d_in[1];
    const float* gn1b  = (const float*)d_in[2];
    const float* W1    = (const float*)d_in[3];
    const float* b1    = (const float*)d_in[4];
    const float* gn2w  = (const float*)d_in[5];
    const float* gn2b  = (const float*)d_in[6];
    const float* W2    = (const float*)d_in[7];
    const float* b2    = (const float*)d_in[8];
    const float* Wsk   = (const float*)d_in[9];
    const float* bsk   = (const float*)d_in[10];
    const int*   seg   = (const int*)d_in[11];
    const int*   nbr   = (const int*)d_in[12];

    const int N = in_sizes[0] / 128;
    const int M = in_sizes[12] / 27;

    cudaFuncSetAttribute(k_conv_mma<false>,
                         cudaFuncAttributeMaxDynamicSharedMemorySize, SMEM_SZ);
    cudaFuncSetAttribute(k_conv_mma<true>,
                         cudaFuncAttributeMaxDynamicSharedMemorySize, SMEM_SZ);

    // weight preprocessing (transpose + bf16 hi/lo split)
    k_wsplit<0><<<(27 * 256 * 128 + 255) / 256, 256>>>(W1, 128, 256, 27 * 256 * 128);
    k_wsplit<1><<<(27 * 256 * 256 + 255) / 256, 256>>>(W2, 256, 256, 27 * 256 * 256);
    k_wsplit<2><<<(256 * 128 + 255) / 256, 256>>>(Wsk, 128, 256, 256 * 128);

    // pooling accumulators
    k_zero<<<(M * 128 + 255) / 256, 256>>>(M);
    // GroupNorm-1 stats
    k_gn_partial<128, false><<<NPART, 128>>>(feats, N);
    k_gn_reduce<<<1, 64>>>(1.f / (4.f * (float)N), 0);
    // silu(gn1(x)) + pooling
    k_act_pool<<<N, 128>>>(feats, gn1w, gn1b, seg);
    // means + bf16 splits
    k_finalize<<<(M * 128 + 255) / 256, 256>>>(M);
    // conv1 (HMMA)
    const int gm = (M + 127) >> 7;
    k_conv_mma<false><<<dim3(gm, 2), 256, SMEM_SZ>>>(nbr, b1, nullptr, nullptr, M);
    // GroupNorm-2 stats
    k_gn_partial<256, true><<<NPART, 256>>>(nullptr, M);
    k_gn_reduce<<<1, 64>>>(1.f / (8.f * (float)M), 1);
    // h2 = silu(gn2(h1)) -> bf16 splits
    k_act2<<<(M * 256 + 255) / 256, 256>>>(gn2w, gn2b, M);
    // conv2 + fused skip (HMMA) -> d_out
    k_conv_mma<true><<<dim3(gm, 2), 256, SMEM_SZ>>>(nbr, b2, bsk, (float*)d_out, M);
}

// round 13
// speedup vs baseline: 3.1912x; 1.1567x over previous
#include <cuda_runtime.h>
#include <cuda_bf16.h>
#include <math.h>
#include <stdint.h>

#define NPART 1024
#define MAX_M 204800   // M <= N = 200000

// ---------------- scratch (device globals: allocation-free) ----------------
__device__ float g_hd[(size_t)MAX_M * 128];
__device__ float g_xd[(size_t)MAX_M * 128];
__device__ float g_cnt[MAX_M];
__device__ float g_h1[(size_t)MAX_M * 256];
__device__ float g_part[NPART * 64];
__device__ float g_stats1[64];
__device__ float g_stats2[64];
// bf16 hi/lo split activations
__device__ __nv_bfloat16 g_hdh[(size_t)MAX_M * 128];
__device__ __nv_bfloat16 g_hdl[(size_t)MAX_M * 128];
__device__ __nv_bfloat16 g_xdh[(size_t)MAX_M * 128];
__device__ __nv_bfloat16 g_xdl[(size_t)MAX_M * 128];
__device__ __nv_bfloat16 g_h2h[(size_t)MAX_M * 256];
__device__ __nv_bfloat16 g_h2l[(size_t)MAX_M * 256];
// split + transposed weights, layout [tap][cout][cin]
__device__ __nv_bfloat16 g_W1h[27 * 256 * 128];
__device__ __nv_bfloat16 g_W1l[27 * 256 * 128];
__device__ __nv_bfloat16 g_W2h[27 * 256 * 256];
__device__ __nv_bfloat16 g_W2l[27 * 256 * 256];
__device__ __nv_bfloat16 g_Wsh[256 * 128];
__device__ __nv_bfloat16 g_Wsl[256 * 128];

// ---------------- PTX helpers (portable sm_80+ paths only) ----------------
__device__ __forceinline__ uint32_t s2u(const void* p) {
    uint32_t a;
    asm("{ .reg .u64 t; cvta.to.shared.u64 t, %1; cvt.u32.u64 %0, t; }" : "=r"(a) : "l"(p));
    return a;
}
__device__ __forceinline__ void cpa(uint32_t dst, const void* src, unsigned sz) {
    asm volatile("cp.async.cg.shared.global [%0], [%1], 16, %2;"
                 :: "r"(dst), "l"(src), "r"(sz) : "memory");
}
__device__ __forceinline__ void cp_commit() {
    asm volatile("cp.async.commit_group;" ::: "memory");
}
__device__ __forceinline__ void cp_wait1() {
    asm volatile("cp.async.wait_group 1;" ::: "memory");
}
__device__ __forceinline__ void ldsm4(uint32_t a, uint32_t* r) {
    asm volatile("ldmatrix.sync.aligned.m8n8.x4.shared.b16 {%0,%1,%2,%3}, [%4];"
                 : "=r"(r[0]), "=r"(r[1]), "=r"(r[2]), "=r"(r[3]) : "r"(a));
}
__device__ __forceinline__ void mma16816(float* d, const uint32_t* a,
                                         uint32_t b0, uint32_t b1) {
    asm volatile(
        "mma.sync.aligned.m16n8k16.row.col.f32.bf16.bf16.f32 "
        "{%0,%1,%2,%3},{%4,%5,%6,%7},{%8,%9},{%0,%1,%2,%3};"
        : "+f"(d[0]), "+f"(d[1]), "+f"(d[2]), "+f"(d[3])
        : "r"(a[0]), "r"(a[1]), "r"(a[2]), "r"(a[3]), "r"(b0), "r"(b1));
}
#define SWZ(x) ((x) ^ (((x) >> 3) & 0x70))

// ---------------- small kernels ----------------
__global__ void k_zero(int M) {
    int i = blockIdx.x * 256 + threadIdx.x;   // float4 index
    float4 z = make_float4(0.f, 0.f, 0.f, 0.f);
    if (i < M * 32) { ((float4*)g_hd)[i] = z; ((float4*)g_xd)[i] = z; }
    if (i < M) g_cnt[i] = 0.f;
}

template <int C, bool FROM_H1>
__global__ void k_gn_partial(const float* __restrict__ Xin, int rows) {
    const float* X = FROM_H1 ? (const float*)g_h1 : Xin;
    const int c = threadIdx.x;
    float s = 0.f, q = 0.f;
    for (int r = blockIdx.x; r < rows; r += NPART) {
        float v = X[(size_t)r * C + c];
        s += v; q += v * v;
    }
    __shared__ float ss[C];
    __shared__ float qq[C];
    ss[c] = s; qq[c] = q;
    __syncthreads();
    if (c < 32) {
        const int cpg = C / 32;
        float S = 0.f, Q = 0.f;
#pragma unroll
        for (int j = 0; j < cpg; ++j) { S += ss[c * cpg + j]; Q += qq[c * cpg + j]; }
        g_part[blockIdx.x * 64 + c]      = S;
        g_part[blockIdx.x * 64 + 32 + c] = Q;
    }
}

__global__ void k_gn_reduce(float inv_n, int which) {
    int t = threadIdx.x;
    float s = 0.f;
    for (int i = 0; i < NPART; ++i) s += g_part[i * 64 + t];
    __shared__ float sm[64];
    sm[t] = s;
    __syncthreads();
    if (t < 32) {
        float mu  = sm[t] * inv_n;
        float var = sm[32 + t] * inv_n - mu * mu;
        float* st = which ? g_stats2 : g_stats1;
        st[t]      = mu;
        st[32 + t] = rsqrtf(var + 1e-5f);
    }
}

__global__ void k_act_pool(const float* __restrict__ feats,
                           const float* __restrict__ w,
                           const float* __restrict__ b,
                           const int* __restrict__ seg) {
    int i = blockIdx.x;
    int c = threadIdx.x;
    float x = feats[(size_t)i * 128 + c];
    int g = c >> 2;
    float h = (x - g_stats1[g]) * g_stats1[32 + g] * w[c] + b[c];
    h = h / (1.f + expf(-h));
    int sgm = seg[i];
    atomicAdd(&g_hd[(size_t)sgm * 128 + c], h);
    atomicAdd(&g_xd[(size_t)sgm * 128 + c], x);
    if (c == 0) atomicAdd(&g_cnt[sgm], 1.f);
}

// means -> bf16 hi/lo splits
__global__ void k_finalize(int M) {
    int idx = blockIdx.x * 256 + threadIdx.x;
    if (idx >= M * 128) return;
    float inv = 1.f / fmaxf(g_cnt[idx >> 7], 1.f);
    float hv = g_hd[idx] * inv;
    float xv = g_xd[idx] * inv;
    __nv_bfloat16 hh = __float2bfloat16(hv);
    __nv_bfloat16 xh = __float2bfloat16(xv);
    g_hdh[idx] = hh; g_hdl[idx] = __float2bfloat16(hv - __bfloat162float(hh));
    g_xdh[idx] = xh; g_xdl[idx] = __float2bfloat16(xv - __bfloat162float(xh));
}

// h2 = silu(gn2(h1)) -> bf16 hi/lo
__global__ void k_act2(const float* __restrict__ w, const float* __restrict__ b, int M) {
    int idx = blockIdx.x * 256 + threadIdx.x;
    if (idx >= M * 256) return;
    int c = idx & 255, g = c >> 3;
    float v = g_h1[idx];
    float h = (v - g_stats2[g]) * g_stats2[32 + g] * w[c] + b[c];
    h = h / (1.f + expf(-h));
    __nv_bfloat16 hh = __float2bfloat16(h);
    g_h2h[idx] = hh;
    g_h2l[idx] = __float2bfloat16(h - __bfloat162float(hh));
}

// W [tap][cin][cout] fp32 -> [tap][cout][cin] bf16 hi/lo
template <int WHICH>
__global__ void k_wsplit(const float* __restrict__ W, int CIN, int COUT, int total) {
    __nv_bfloat16* Oh = WHICH == 0 ? g_W1h : WHICH == 1 ? g_W2h : g_Wsh;
    __nv_bfloat16* Ol = WHICH == 0 ? g_W1l : WHICH == 1 ? g_W2l : g_Wsl;
    int idx = blockIdx.x * 256 + threadIdx.x;
    if (idx >= total) return;
    int ci = idx % CIN;
    int t = idx / CIN;
    int co = t % COUT;
    int k = t / COUT;
    float v = W[((size_t)k * CIN + ci) * COUT + co];
    __nv_bfloat16 h = __float2bfloat16(v);
    Oh[idx] = h;
    Ol[idx] = __float2bfloat16(v - __bfloat162float(h));
}

// ---------------- HMMA 27-tap gather GEMM ----------------
// CTA 128x128, 8 warps (warp = 32m x 64n), BK=64, 3-stage cp.async pipeline
// (ONE barrier per chunk), bf16 hi/lo 3-pass split with per-ks fragment reuse.
#define STG 65536           // Ah 16K | Al 16K | Bh 16K | Bl 16K
#define RIDX_OFF (3 * STG)
#define SMEM_SZ (3 * STG + 28 * 128 * 4)

template <bool SECOND>
__global__ void __launch_bounds__(256, 1)
k_conv_mma(const int* __restrict__ nbr, const float* __restrict__ bias,
           const float* __restrict__ bsk, float* __restrict__ out_arg, int M) {
    extern __shared__ char smem[];
    const uint32_t sb = s2u(smem);
    int* ridx = (int*)(smem + RIDX_OFF);      // [TT][128]
    const int tid = threadIdx.x, lane = tid & 31, wid = tid >> 5;
    const int bn0 = blockIdx.x << 7, bm0 = blockIdx.y << 7;   // x = N-half (L2 reuse)
    const int mbase = (wid >> 1) * 32, nbase = (wid & 1) * 64;
    float* out = SECOND ? out_arg : (float*)g_h1;
    const int NC = SECOND ? 110 : 54;
    const int TT = SECOND ? 28 : 27;

    // ---- preload the full neighbor table once ----
    for (int e = tid; e < TT * 128; e += 256) {
        int row = e & 127, tap = e >> 7;
        int r = bm0 + row;
        int v = -1;
        if (r < M) v = (SECOND && tap == 27) ? r : nbr[r * 27 + tap];
        ridx[e] = v;
    }
    __syncthreads();

    float acc[2][8][4];
#pragma unroll
    for (int i = 0; i < 2; ++i)
#pragma unroll
        for (int j = 0; j < 8; ++j)
#pragma unroll
            for (int q = 0; q < 4; ++q) acc[i][j][q] = 0.f;

    // ldmatrix lane geometry (identical to the R10 passing kernel)
    const int lj = lane >> 3, lr = lane & 7;
    int arow[2], brow[4];
#pragma unroll
    for (int mt = 0; mt < 2; ++mt) arow[mt] = mbase + mt * 16 + (lj & 1) * 8 + lr;
#pragma unroll
    for (int p = 0; p < 4; ++p) brow[p] = nbase + p * 16 + (lj >> 1) * 8 + lr;
    const int akb = (lj >> 1) * 16, bkb = (lj & 1) * 16;

    auto issue = [&](int c) {
        int tap, cc, Kd;
        const __nv_bfloat16 *Xh, *Xl, *Wh, *Wl;
        if (SECOND) {
            if (c < 108) {
                tap = c >> 2; cc = c & 3; Kd = 256;
                Xh = g_h2h; Xl = g_h2l;
                size_t wo = ((size_t)tap * 256 + bn0) * 256;
                Wh = g_W2h + wo; Wl = g_W2l + wo;
            } else {
                tap = 27; cc = c - 108; Kd = 128;
                Xh = g_xdh; Xl = g_xdl;
                size_t wo = (size_t)bn0 * 128;
                Wh = g_Wsh + wo; Wl = g_Wsl + wo;
            }
        } else {
            tap = c >> 1; cc = c & 1; Kd = 128;
            Xh = g_hdh; Xl = g_hdl;
            size_t wo = ((size_t)tap * 256 + bn0) * 128;
            Wh = g_W1h + wo; Wl = g_W1l + wo;
        }
        const uint32_t S = sb + (c % 3) * STG;
        const int row = tid >> 1;
        int gi = ridx[tap * 128 + row];
        unsigned sz = (gi >= 0) ? 16u : 0u;
        size_t xo = (size_t)(gi >= 0 ? gi : 0) * Kd + cc * 64;
        size_t woff = (size_t)row * Kd + cc * 64;
#pragma unroll
        for (int i = 0; i < 4; ++i) {
            int seg = (tid & 1) * 4 + i;
            uint32_t off = SWZ(row * 128 + seg * 16);
            cpa(S + off,         Xh + xo + seg * 8, sz);
            cpa(S + 16384 + off, Xl + xo + seg * 8, sz);
            cpa(S + 32768 + off, Wh + woff + seg * 8, 16u);
            cpa(S + 49152 + off, Wl + woff + seg * 8, 16u);
        }
    };

    issue(0); cp_commit();
    issue(1); cp_commit();

    for (int c = 0; c < NC; ++c) {
        cp_wait1();          // own groups for stage c complete (<=1 pending)
        __syncthreads();     // all threads' stage-c data visible; stage c-1 free

        const uint32_t Sb = sb + (c % 3) * STG;
#pragma unroll
        for (int ks = 0; ks < 4; ++ks) {
            uint32_t ah[2][4], al[2][4], bh[4][4], bl[4][4];
#pragma unroll
            for (int mt = 0; mt < 2; ++mt) {
                uint32_t aA = Sb + arow[mt] * 128 +
                              ((ks * 32 + akb) ^ ((arow[mt] & 7) * 16));
                ldsm4(aA, ah[mt]);
                ldsm4(aA + 16384, al[mt]);
            }
#pragma unroll
            for (int p = 0; p < 4; ++p) {
                uint32_t aB = Sb + 32768 + brow[p] * 128 +
                              ((ks * 32 + bkb) ^ ((brow[p] & 7) * 16));
                ldsm4(aB, bh[p]);
                ldsm4(aB + 16384, bl[p]);
            }
#pragma unroll
            for (int mt = 0; mt < 2; ++mt)
#pragma unroll
                for (int nt = 0; nt < 8; ++nt) {
                    uint32_t h0 = bh[nt >> 1][(nt & 1) * 2], h1 = bh[nt >> 1][(nt & 1) * 2 + 1];
                    uint32_t l0 = bl[nt >> 1][(nt & 1) * 2], l1 = bl[nt >> 1][(nt & 1) * 2 + 1];
                    mma16816(acc[mt][nt], ah[mt], h0, h1);   // hh
                    mma16816(acc[mt][nt], ah[mt], l0, l1);   // hl
                    mma16816(acc[mt][nt], al[mt], h0, h1);   // lh
                }
        }
        if (c + 2 < NC) issue(c + 2);
        cp_commit();
    }

    // epilogue: registers -> gmem with fused bias
#pragma unroll
    for (int nt = 0; nt < 8; ++nt) {
        int col = bn0 + nbase + nt * 8 + (lane & 3) * 2;
        float bx = bias[col]     + (SECOND ? bsk[col]     : 0.f);
        float by = bias[col + 1] + (SECOND ? bsk[col + 1] : 0.f);
#pragma unroll
        for (int mt = 0; mt < 2; ++mt) {
            int r0 = bm0 + mbase + mt * 16 + (lane >> 2);
            if (r0 < M) {
                float2 v = make_float2(acc[mt][nt][0] + bx, acc[mt][nt][1] + by);
                *(float2*)(out + (size_t)r0 * 256 + col) = v;
            }
            int r1 = r0 + 8;
            if (r1 < M) {
                float2 v = make_float2(acc[mt][nt][2] + bx, acc[mt][nt][3] + by);
                *(float2*)(out + (size_t)r1 * 256 + col) = v;
            }
        }
    }
}

// ---------------- launch ----------------
extern "C" void kernel_launch(void* const* d_in, const int* in_sizes, int n_in,
                              void* d_out, int out_size) {
    const float* feats = (const float*)d_in[0];
    const float* gn1w  = (const float*)d_in[1];
    const float* gn1b  = (const float*)d_in[2];
    const float* W1    = (const float*)d_in[3];
    const float* b1    = (const float*)d_in[4];
    const float* gn2w  = (const float*)d_in[5];
    const float* gn2b  = (const float*)d_in[6];
    const float* W2    = (const float*)d_in[7];
    const float* b2    = (const float*)d_in[8];
    const float* Wsk   = (const float*)d_in[9];
    const float* bsk   = (const float*)d_in[10];
    const int*   seg   = (const int*)d_in[11];
    const int*   nbr   = (const int*)d_in[12];

    const int N = in_sizes[0] / 128;
    const int M = in_sizes[12] / 27;

    cudaFuncSetAttribute(k_conv_mma<false>,
                         cudaFuncAttributeMaxDynamicSharedMemorySize, SMEM_SZ);
    cudaFuncSetAttribute(k_conv_mma<true>,
                         cudaFuncAttributeMaxDynamicSharedMemorySize, SMEM_SZ);

    // weight preprocessing (transpose + bf16 hi/lo split)
    k_wsplit<0><<<(27 * 256 * 128 + 255) / 256, 256>>>(W1, 128, 256, 27 * 256 * 128);
    k_wsplit<1><<<(27 * 256 * 256 + 255) / 256, 256>>>(W2, 256, 256, 27 * 256 * 256);
    k_wsplit<2><<<(256 * 128 + 255) / 256, 256>>>(Wsk, 128, 256, 256 * 128);

    // pooling accumulators
    k_zero<<<(M * 32 + 255) / 256, 256>>>(M);
    // GroupNorm-1 stats
    k_gn_partial<128, false><<<NPART, 128>>>(feats, N);
    k_gn_reduce<<<1, 64>>>(1.f / (4.f * (float)N), 0);
    // silu(gn1(x)) + pooling
    k_act_pool<<<N, 128>>>(feats, gn1w, gn1b, seg);
    // means + bf16 splits
    k_finalize<<<(M * 128 + 255) / 256, 256>>>(M);
    // conv1 (HMMA)
    const int gm = (M + 127) >> 7;
    k_conv_mma<false><<<dim3(2, gm), 256, SMEM_SZ>>>(nbr, b1, nullptr, nullptr, M);
    // GroupNorm-2 stats
    k_gn_partial<256, true><<<NPART, 256>>>(nullptr, M);
    k_gn_reduce<<<1, 64>>>(1.f / (8.f * (float)M), 1);
    // h2 = silu(gn2(h1)) -> bf16 splits
    k_act2<<<(M * 256 + 255) / 256, 256>>>(gn2w, gn2b, M);
    // conv2 + fused skip (HMMA) -> d_out
    k_conv_mma<true><<<dim3(2, gm), 256, SMEM_SZ>>>(nbr, b2, bsk, (float*)d_out, M);
}

// round 15
// speedup vs baseline: 4.5569x; 1.4280x over previous
#include <cuda_runtime.h>
#include <cuda_fp16.h>
#include <math.h>
#include <stdint.h>

#define NPART 1024
#define MAX_M 204800   // M <= N = 200000

// ---------------- scratch (device globals: allocation-free) ----------------
__device__ float g_hd[(size_t)MAX_M * 128];
__device__ float g_xd[(size_t)MAX_M * 128];
__device__ float g_cnt[MAX_M];
__device__ float g_h1[(size_t)MAX_M * 256];
__device__ float g_part[NPART * 64];
__device__ float g_stats1[64];
__device__ float g_stats2[64];
// fp16 hi/lo split activations
__device__ __half g_hdh[(size_t)MAX_M * 128];
__device__ __half g_hdl[(size_t)MAX_M * 128];
__device__ __half g_xdh[(size_t)MAX_M * 128];
__device__ __half g_xdl[(size_t)MAX_M * 128];
__device__ __half g_h2h[(size_t)MAX_M * 256];
__device__ __half g_h2l[(size_t)MAX_M * 256];
// fp16 transposed weights, layout [tap][cout][cin] (single precision level)
__device__ __half g_W1f[27 * 256 * 128];
__device__ __half g_W2f[27 * 256 * 256];
__device__ __half g_Wsf[256 * 128];

// ---------------- PTX helpers (portable sm_80+ paths only) ----------------
__device__ __forceinline__ uint32_t s2u(const void* p) {
    uint32_t a;
    asm("{ .reg .u64 t; cvta.to.shared.u64 t, %1; cvt.u32.u64 %0, t; }" : "=r"(a) : "l"(p));
    return a;
}
__device__ __forceinline__ void cpa(uint32_t dst, const void* src, unsigned sz) {
    asm volatile("cp.async.cg.shared.global [%0], [%1], 16, %2;"
                 :: "r"(dst), "l"(src), "r"(sz) : "memory");
}
__device__ __forceinline__ void cp_commit() {
    asm volatile("cp.async.commit_group;" ::: "memory");
}
__device__ __forceinline__ void cp_wait2() {
    asm volatile("cp.async.wait_group 2;" ::: "memory");
}
__device__ __forceinline__ void ldsm4(uint32_t a, uint32_t* r) {
    asm volatile("ldmatrix.sync.aligned.m8n8.x4.shared.b16 {%0,%1,%2,%3}, [%4];"
                 : "=r"(r[0]), "=r"(r[1]), "=r"(r[2]), "=r"(r[3]) : "r"(a));
}
__device__ __forceinline__ void mma16816(float* d, const uint32_t* a,
                                         uint32_t b0, uint32_t b1) {
    asm volatile(
        "mma.sync.aligned.m16n8k16.row.col.f32.f16.f16.f32 "
        "{%0,%1,%2,%3},{%4,%5,%6,%7},{%8,%9},{%0,%1,%2,%3};"
        : "+f"(d[0]), "+f"(d[1]), "+f"(d[2]), "+f"(d[3])
        : "r"(a[0]), "r"(a[1]), "r"(a[2]), "r"(a[3]), "r"(b0), "r"(b1));
}
#define SWZ(x) ((x) ^ (((x) >> 3) & 0x70))

// ---------------- small kernels ----------------
__global__ void k_zero(int M) {
    int i = blockIdx.x * 256 + threadIdx.x;   // float4 index
    float4 z = make_float4(0.f, 0.f, 0.f, 0.f);
    if (i < M * 32) { ((float4*)g_hd)[i] = z; ((float4*)g_xd)[i] = z; }
    if (i < M) g_cnt[i] = 0.f;
}

template <int C, bool FROM_H1>
__global__ void k_gn_partial(const float* __restrict__ Xin, int rows) {
    const float* X = FROM_H1 ? (const float*)g_h1 : Xin;
    const int c = threadIdx.x;
    float s = 0.f, q = 0.f;
    for (int r = blockIdx.x; r < rows; r += NPART) {
        float v = X[(size_t)r * C + c];
        s += v; q += v * v;
    }
    __shared__ float ss[C];
    __shared__ float qq[C];
    ss[c] = s; qq[c] = q;
    __syncthreads();
    if (c < 32) {
        const int cpg = C / 32;
        float S = 0.f, Q = 0.f;
#pragma unroll
        for (int j = 0; j < cpg; ++j) { S += ss[c * cpg + j]; Q += qq[c * cpg + j]; }
        g_part[blockIdx.x * 64 + c]      = S;
        g_part[blockIdx.x * 64 + 32 + c] = Q;
    }
}

__global__ void k_gn_reduce(float inv_n, int which) {
    int t = threadIdx.x;
    float s = 0.f;
    for (int i = 0; i < NPART; ++i) s += g_part[i * 64 + t];
    __shared__ float sm[64];
    sm[t] = s;
    __syncthreads();
    if (t < 32) {
        float mu  = sm[t] * inv_n;
        float var = sm[32 + t] * inv_n - mu * mu;
        float* st = which ? g_stats2 : g_stats1;
        st[t]      = mu;
        st[32 + t] = rsqrtf(var + 1e-5f);
    }
}

__global__ void k_act_pool(const float* __restrict__ feats,
                           const float* __restrict__ w,
                           const float* __restrict__ b,
                           const int* __restrict__ seg) {
    int i = blockIdx.x;
    int c = threadIdx.x;
    float x = feats[(size_t)i * 128 + c];
    int g = c >> 2;
    float h = (x - g_stats1[g]) * g_stats1[32 + g] * w[c] + b[c];
    h = h / (1.f + expf(-h));
    int sgm = seg[i];
    atomicAdd(&g_hd[(size_t)sgm * 128 + c], h);
    atomicAdd(&g_xd[(size_t)sgm * 128 + c], x);
    if (c == 0) atomicAdd(&g_cnt[sgm], 1.f);
}

// means -> fp16 hi/lo splits
__global__ void k_finalize(int M) {
    int idx = blockIdx.x * 256 + threadIdx.x;
    if (idx >= M * 128) return;
    float inv = 1.f / fmaxf(g_cnt[idx >> 7], 1.f);
    float hv = g_hd[idx] * inv;
    float xv = g_xd[idx] * inv;
    __half hh = __float2half_rn(hv);
    __half xh = __float2half_rn(xv);
    g_hdh[idx] = hh; g_hdl[idx] = __float2half_rn(hv - __half2float(hh));
    g_xdh[idx] = xh; g_xdl[idx] = __float2half_rn(xv - __half2float(xh));
}

// h2 = silu(gn2(h1)) -> fp16 hi/lo
__global__ void k_act2(const float* __restrict__ w, const float* __restrict__ b, int M) {
    int idx = blockIdx.x * 256 + threadIdx.x;
    if (idx >= M * 256) return;
    int c = idx & 255, g = c >> 3;
    float v = g_h1[idx];
    float h = (v - g_stats2[g]) * g_stats2[32 + g] * w[c] + b[c];
    h = h / (1.f + expf(-h));
    __half hh = __float2half_rn(h);
    g_h2h[idx] = hh;
    g_h2l[idx] = __float2half_rn(h - __half2float(hh));
}

// W [tap][cin][cout] fp32 -> [tap][cout][cin] fp16
template <int WHICH>
__global__ void k_wsplit(const float* __restrict__ W, int CIN, int COUT, int total) {
    __half* O = WHICH == 0 ? g_W1f : WHICH == 1 ? g_W2f : g_Wsf;
    int idx = blockIdx.x * 256 + threadIdx.x;
    if (idx >= total) return;
    int ci = idx % CIN;
    int t = idx / CIN;
    int co = t % COUT;
    int k = t / COUT;
    O[idx] = __float2half_rn(W[((size_t)k * CIN + ci) * COUT + co]);
}

// ---------------- HMMA 27-tap gather GEMM ----------------
// CTA 128x128, 8 warps (warp = 32m x 64n), BK=64, 4-stage cp.async pipeline
// (one barrier per chunk), fp16 asymmetric split: A = hi+lo fp16, B = fp16.
// acc += a_hi*w + a_lo*w  (error = weight fp16 rounding ~2^-12)
#define STG 49152           // Ah 16K | Al 16K | B 16K
#define NSTG 4
#define RIDX_OFF (NSTG * STG)
#define SMEM_SZ (NSTG * STG + 28 * 128 * 4)

template <bool SECOND>
__global__ void __launch_bounds__(256, 1)
k_conv_mma(const int* __restrict__ nbr, const float* __restrict__ bias,
           const float* __restrict__ bsk, float* __restrict__ out_arg, int M) {
    extern __shared__ char smem[];
    const uint32_t sb = s2u(smem);
    int* ridx = (int*)(smem + RIDX_OFF);      // [TT][128]
    const int tid = threadIdx.x, lane = tid & 31, wid = tid >> 5;
    const int bn0 = blockIdx.x << 7, bm0 = blockIdx.y << 7;   // x = N-half (L2 reuse)
    const int mbase = (wid >> 1) * 32, nbase = (wid & 1) * 64;
    float* out = SECOND ? out_arg : (float*)g_h1;
    const int NC = SECOND ? 110 : 54;
    const int TT = SECOND ? 28 : 27;

    // ---- preload the full neighbor table once ----
    for (int e = tid; e < TT * 128; e += 256) {
        int row = e & 127, tap = e >> 7;
        int r = bm0 + row;
        int v = -1;
        if (r < M) v = (SECOND && tap == 27) ? r : nbr[r * 27 + tap];
        ridx[e] = v;
    }
    __syncthreads();

    float acc[2][8][4];
#pragma unroll
    for (int i = 0; i < 2; ++i)
#pragma unroll
        for (int j = 0; j < 8; ++j)
#pragma unroll
            for (int q = 0; q < 4; ++q) acc[i][j][q] = 0.f;

    // ldmatrix lane geometry
    const int lj = lane >> 3, lr = lane & 7;
    int arow[2], brow[4];
#pragma unroll
    for (int mt = 0; mt < 2; ++mt) arow[mt] = mbase + mt * 16 + (lj & 1) * 8 + lr;
#pragma unroll
    for (int p = 0; p < 4; ++p) brow[p] = nbase + p * 16 + (lj >> 1) * 8 + lr;
    const int akb = (lj >> 1) * 16, bkb = (lj & 1) * 16;

    auto issue = [&](int c) {
        int tap, cc, Kd;
        const __half *Xh, *Xl, *Wf;
        if (SECOND) {
            if (c < 108) {
                tap = c >> 2; cc = c & 3; Kd = 256;
                Xh = g_h2h; Xl = g_h2l;
                Wf = g_W2f + ((size_t)tap * 256 + bn0) * 256;
            } else {
                tap = 27; cc = c - 108; Kd = 128;
                Xh = g_xdh; Xl = g_xdl;
                Wf = g_Wsf + (size_t)bn0 * 128;
            }
        } else {
            tap = c >> 1; cc = c & 1; Kd = 128;
            Xh = g_hdh; Xl = g_hdl;
            Wf = g_W1f + ((size_t)tap * 256 + bn0) * 128;
        }
        const uint32_t S = sb + (c % NSTG) * STG;
        const int row = tid >> 1;
        int gi = ridx[tap * 128 + row];
        unsigned sz = (gi >= 0) ? 16u : 0u;
        size_t xo = (size_t)(gi >= 0 ? gi : 0) * Kd + cc * 64;
        size_t woff = (size_t)row * Kd + cc * 64;
#pragma unroll
        for (int i = 0; i < 4; ++i) {
            int seg = (tid & 1) * 4 + i;
            uint32_t off = SWZ(row * 128 + seg * 16);
            cpa(S + off,         Xh + xo + seg * 8, sz);
            cpa(S + 16384 + off, Xl + xo + seg * 8, sz);
            cpa(S + 32768 + off, Wf + woff + seg * 8, 16u);
        }
    };

    issue(0); cp_commit();
    issue(1); cp_commit();
    issue(2); cp_commit();

    for (int c = 0; c < NC; ++c) {
        cp_wait2();          // stage c complete (<=2 groups pending)
        __syncthreads();     // all threads' stage-c data visible; stage c-1 free

        const uint32_t Sb = sb + (c % NSTG) * STG;
#pragma unroll
        for (int ks = 0; ks < 4; ++ks) {
            uint32_t ah[2][4], al[2][4], b[4][4];
#pragma unroll
            for (int mt = 0; mt < 2; ++mt) {
                uint32_t aA = Sb + arow[mt] * 128 +
                              ((ks * 32 + akb) ^ ((arow[mt] & 7) * 16));
                ldsm4(aA, ah[mt]);
                ldsm4(aA + 16384, al[mt]);
            }
#pragma unroll
            for (int p = 0; p < 4; ++p) {
                uint32_t aB = Sb + 32768 + brow[p] * 128 +
                              ((ks * 32 + bkb) ^ ((brow[p] & 7) * 16));
                ldsm4(aB, b[p]);
            }
#pragma unroll
            for (int mt = 0; mt < 2; ++mt)
#pragma unroll
                for (int nt = 0; nt < 8; ++nt) {
                    uint32_t b0 = b[nt >> 1][(nt & 1) * 2], b1 = b[nt >> 1][(nt & 1) * 2 + 1];
                    mma16816(acc[mt][nt], ah[mt], b0, b1);   // a_hi * w
                    mma16816(acc[mt][nt], al[mt], b0, b1);   // a_lo * w
                }
        }
        if (c + 3 < NC) issue(c + 3);
        cp_commit();
    }

    // epilogue: registers -> gmem with fused bias
#pragma unroll
    for (int nt = 0; nt < 8; ++nt) {
        int col = bn0 + nbase + nt * 8 + (lane & 3) * 2;
        float bx = bias[col]     + (SECOND ? bsk[col]     : 0.f);
        float by = bias[col + 1] + (SECOND ? bsk[col + 1] : 0.f);
#pragma unroll
        for (int mt = 0; mt < 2; ++mt) {
            int r0 = bm0 + mbase + mt * 16 + (lane >> 2);
            if (r0 < M) {
                float2 v = make_float2(acc[mt][nt][0] + bx, acc[mt][nt][1] + by);
                *(float2*)(out + (size_t)r0 * 256 + col) = v;
            }
            int r1 = r0 + 8;
            if (r1 < M) {
                float2 v = make_float2(acc[mt][nt][2] + bx, acc[mt][nt][3] + by);
                *(float2*)(out + (size_t)r1 * 256 + col) = v;
            }
        }
    }
}

// ---------------- launch ----------------
extern "C" void kernel_launch(void* const* d_in, const int* in_sizes, int n_in,
                              void* d_out, int out_size) {
    const float* feats = (const float*)d_in[0];
    const float* gn1w  = (const float*)d_in[1];
    const float* gn1b  = (const float*)d_in[2];
    const float* W1    = (const float*)d_in[3];
    const float* b1    = (const float*)d_in[4];
    const float* gn2w  = (const float*)d_in[5];
    const float* gn2b  = (const float*)d_in[6];
    const float* W2    = (const float*)d_in[7];
    const float* b2    = (const float*)d_in[8];
    const float* Wsk   = (const float*)d_in[9];
    const float* bsk   = (const float*)d_in[10];
    const int*   seg   = (const int*)d_in[11];
    const int*   nbr   = (const int*)d_in[12];

    const int N = in_sizes[0] / 128;
    const int M = in_sizes[12] / 27;

    cudaFuncSetAttribute(k_conv_mma<false>,
                         cudaFuncAttributeMaxDynamicSharedMemorySize, SMEM_SZ);
    cudaFuncSetAttribute(k_conv_mma<true>,
                         cudaFuncAttributeMaxDynamicSharedMemorySize, SMEM_SZ);

    // weight preprocessing (transpose + fp16 round)
    k_wsplit<0><<<(27 * 256 * 128 + 255) / 256, 256>>>(W1, 128, 256, 27 * 256 * 128);
    k_wsplit<1><<<(27 * 256 * 256 + 255) / 256, 256>>>(W2, 256, 256, 27 * 256 * 256);
    k_wsplit<2><<<(256 * 128 + 255) / 256, 256>>>(Wsk, 128, 256, 256 * 128);

    // pooling accumulators
    k_zero<<<(M * 32 + 255) / 256, 256>>>(M);
    // GroupNorm-1 stats
    k_gn_partial<128, false><<<NPART, 128>>>(feats, N);
    k_gn_reduce<<<1, 64>>>(1.f / (4.f * (float)N), 0);
    // silu(gn1(x)) + pooling
    k_act_pool<<<N, 128>>>(feats, gn1w, gn1b, seg);
    // means + fp16 splits
    k_finalize<<<(M * 128 + 255) / 256, 256>>>(M);
    // conv1 (HMMA fp16 2-pass)
    const int gm = (M + 127) >> 7;
    k_conv_mma<false><<<dim3(2, gm), 256, SMEM_SZ>>>(nbr, b1, nullptr, nullptr, M);
    // GroupNorm-2 stats
    k_gn_partial<256, true><<<NPART, 256>>>(nullptr, M);
    k_gn_reduce<<<1, 64>>>(1.f / (8.f * (float)M), 1);
    // h2 = silu(gn2(h1)) -> fp16 splits
    k_act2<<<(M * 256 + 255) / 256, 256>>>(gn2w, gn2b, M);
    // conv2 + fused skip (HMMA fp16 2-pass) -> d_out
    k_conv_mma<true><<<dim3(2, gm), 256, SMEM_SZ>>>(nbr, b2, bsk, (float*)d_out, M);
}

// round 17
// speedup vs baseline: 8.4334x; 1.8507x over previous
#include <cuda_runtime.h>
#include <cuda_fp16.h>
#include <math.h>
#include <stdint.h>

#define NPART 1024
#define MAX_M 204800   // M <= N = 200000

// ---------------- scratch (device globals: allocation-free) ----------------
__device__ float g_hd[(size_t)MAX_M * 128];
__device__ float g_xd[(size_t)MAX_M * 128];
__device__ float g_cnt[MAX_M];
__device__ float g_h1[(size_t)MAX_M * 256];
__device__ float g_part[NPART * 64];
__device__ float g_stats1[64];
__device__ float g_stats2[64];
// fp16 activations (single precision level)
__device__ __half g_hdh[(size_t)MAX_M * 128];
__device__ __half g_xdh[(size_t)MAX_M * 128];
__device__ __half g_h2h[(size_t)MAX_M * 256];
// fp16 transposed weights, layout [tap][cout][cin]
__device__ __half g_W1f[27 * 256 * 128];
__device__ __half g_W2f[27 * 256 * 256];
__device__ __half g_Wsf[256 * 128];

// ---------------- PTX helpers (portable sm_80+ paths only) ----------------
__device__ __forceinline__ uint32_t s2u(const void* p) {
    uint32_t a;
    asm("{ .reg .u64 t; cvta.to.shared.u64 t, %1; cvt.u32.u64 %0, t; }" : "=r"(a) : "l"(p));
    return a;
}
__device__ __forceinline__ void cpa(uint32_t dst, const void* src, unsigned sz) {
    asm volatile("cp.async.cg.shared.global [%0], [%1], 16, %2;"
                 :: "r"(dst), "l"(src), "r"(sz) : "memory");
}
__device__ __forceinline__ void cp_commit() {
    asm volatile("cp.async.commit_group;" ::: "memory");
}
__device__ __forceinline__ void cp_wait1() {
    asm volatile("cp.async.wait_group 1;" ::: "memory");
}
__device__ __forceinline__ void ldsm4(uint32_t a, uint32_t* r) {
    asm volatile("ldmatrix.sync.aligned.m8n8.x4.shared.b16 {%0,%1,%2,%3}, [%4];"
                 : "=r"(r[0]), "=r"(r[1]), "=r"(r[2]), "=r"(r[3]) : "r"(a));
}
__device__ __forceinline__ void mma16816(float* d, const uint32_t* a,
                                         uint32_t b0, uint32_t b1) {
    asm volatile(
        "mma.sync.aligned.m16n8k16.row.col.f32.f16.f16.f32 "
        "{%0,%1,%2,%3},{%4,%5,%6,%7},{%8,%9},{%0,%1,%2,%3};"
        : "+f"(d[0]), "+f"(d[1]), "+f"(d[2]), "+f"(d[3])
        : "r"(a[0]), "r"(a[1]), "r"(a[2]), "r"(a[3]), "r"(b0), "r"(b1));
}
#define SWZ(x) ((x) ^ (((x) >> 3) & 0x70))

// ---------------- small kernels ----------------
__global__ void k_zero(int M) {
    int i = blockIdx.x * 256 + threadIdx.x;   // float4 index
    float4 z = make_float4(0.f, 0.f, 0.f, 0.f);
    if (i < M * 32) { ((float4*)g_hd)[i] = z; ((float4*)g_xd)[i] = z; }
    if (i < M) g_cnt[i] = 0.f;
}

template <int C, bool FROM_H1>
__global__ void k_gn_partial(const float* __restrict__ Xin, int rows) {
    const float* X = FROM_H1 ? (const float*)g_h1 : Xin;
    const int c = threadIdx.x;
    float s = 0.f, q = 0.f;
    for (int r = blockIdx.x; r < rows; r += NPART) {
        float v = X[(size_t)r * C + c];
        s += v; q += v * v;
    }
    __shared__ float ss[C];
    __shared__ float qq[C];
    ss[c] = s; qq[c] = q;
    __syncthreads();
    if (c < 32) {
        const int cpg = C / 32;
        float S = 0.f, Q = 0.f;
#pragma unroll
        for (int j = 0; j < cpg; ++j) { S += ss[c * cpg + j]; Q += qq[c * cpg + j]; }
        g_part[blockIdx.x * 64 + c]      = S;
        g_part[blockIdx.x * 64 + 32 + c] = Q;
    }
}

__global__ void k_gn_reduce(float inv_n, int which) {
    int t = threadIdx.x;
    float s = 0.f;
    for (int i = 0; i < NPART; ++i) s += g_part[i * 64 + t];
    __shared__ float sm[64];
    sm[t] = s;
    __syncthreads();
    if (t < 32) {
        float mu  = sm[t] * inv_n;
        float var = sm[32 + t] * inv_n - mu * mu;
        float* st = which ? g_stats2 : g_stats1;
        st[t]      = mu;
        st[32 + t] = rsqrtf(var + 1e-5f);
    }
}

__global__ void k_act_pool(const float* __restrict__ feats,
                           const float* __restrict__ w,
                           const float* __restrict__ b,
                           const int* __restrict__ seg) {
    int i = blockIdx.x;
    int c = threadIdx.x;
    float x = feats[(size_t)i * 128 + c];
    int g = c >> 2;
    float h = (x - g_stats1[g]) * g_stats1[32 + g] * w[c] + b[c];
    h = h / (1.f + expf(-h));
    int sgm = seg[i];
    atomicAdd(&g_hd[(size_t)sgm * 128 + c], h);
    atomicAdd(&g_xd[(size_t)sgm * 128 + c], x);
    if (c == 0) atomicAdd(&g_cnt[sgm], 1.f);
}

// means -> fp16
__global__ void k_finalize(int M) {
    int idx = blockIdx.x * 256 + threadIdx.x;
    if (idx >= M * 128) return;
    float inv = 1.f / fmaxf(g_cnt[idx >> 7], 1.f);
    g_hdh[idx] = __float2half_rn(g_hd[idx] * inv);
    g_xdh[idx] = __float2half_rn(g_xd[idx] * inv);
}

// h2 = silu(gn2(h1)) -> fp16
__global__ void k_act2(const float* __restrict__ w, const float* __restrict__ b, int M) {
    int idx = blockIdx.x * 256 + threadIdx.x;
    if (idx >= M * 256) return;
    int c = idx & 255, g = c >> 3;
    float v = g_h1[idx];
    float h = (v - g_stats2[g]) * g_stats2[32 + g] * w[c] + b[c];
    g_h2h[idx] = __float2half_rn(h / (1.f + expf(-h)));
}

// W [tap][cin][cout] fp32 -> [tap][cout][cin] fp16
template <int WHICH>
__global__ void k_wsplit(const float* __restrict__ W, int CIN, int COUT, int total) {
    __half* O = WHICH == 0 ? g_W1f : WHICH == 1 ? g_W2f : g_Wsf;
    int idx = blockIdx.x * 256 + threadIdx.x;
    if (idx >= total) return;
    int ci = idx % CIN;
    int t = idx / CIN;
    int co = t % COUT;
    int k = t / COUT;
    O[idx] = __float2half_rn(W[((size_t)k * CIN + ci) * COUT + co]);
}

// ---------------- HMMA 27-tap gather GEMM ----------------
// CTA 128x128, 8 warps (warp = 32m x 64n), BK=64, single-pass fp16,
// 3-stage cp.async pipeline, 2 CTAs/SM for latency hiding.
#define STG 32768           // A 16K | B 16K
#define NSTG 3
#define RIDX_OFF (NSTG * STG)
#define SMEM_SZ (NSTG * STG + 28 * 128 * 4)

template <bool SECOND>
__global__ void __launch_bounds__(256, 2)
k_conv_mma(const int* __restrict__ nbr, const float* __restrict__ bias,
           const float* __restrict__ bsk, float* __restrict__ out_arg, int M) {
    extern __shared__ char smem[];
    const uint32_t sb = s2u(smem);
    int* ridx = (int*)(smem + RIDX_OFF);      // [TT][128]
    const int tid = threadIdx.x, lane = tid & 31, wid = tid >> 5;
    const int bn0 = blockIdx.x << 7, bm0 = blockIdx.y << 7;   // x = N-half (L2 reuse)
    const int mbase = (wid >> 1) * 32, nbase = (wid & 1) * 64;
    float* out = SECOND ? out_arg : (float*)g_h1;
    const int NC = SECOND ? 110 : 54;
    const int TT = SECOND ? 28 : 27;

    // ---- preload the full neighbor table once ----
    for (int e = tid; e < TT * 128; e += 256) {
        int row = e & 127, tap = e >> 7;
        int r = bm0 + row;
        int v = -1;
        if (r < M) v = (SECOND && tap == 27) ? r : nbr[r * 27 + tap];
        ridx[e] = v;
    }
    __syncthreads();

    float acc[2][8][4];
#pragma unroll
    for (int i = 0; i < 2; ++i)
#pragma unroll
        for (int j = 0; j < 8; ++j)
#pragma unroll
            for (int q = 0; q < 4; ++q) acc[i][j][q] = 0.f;

    // ldmatrix lane geometry
    const int lj = lane >> 3, lr = lane & 7;
    int arow[2], brow[4];
#pragma unroll
    for (int mt = 0; mt < 2; ++mt) arow[mt] = mbase + mt * 16 + (lj & 1) * 8 + lr;
#pragma unroll
    for (int p = 0; p < 4; ++p) brow[p] = nbase + p * 16 + (lj >> 1) * 8 + lr;
    const int akb = (lj >> 1) * 16, bkb = (lj & 1) * 16;

    auto issue = [&](int c) {
        int tap, cc, Kd;
        const __half *Xh, *Wf;
        if (SECOND) {
            if (c < 108) {
                tap = c >> 2; cc = c & 3; Kd = 256;
                Xh = g_h2h;
                Wf = g_W2f + ((size_t)tap * 256 + bn0) * 256;
            } else {
                tap = 27; cc = c - 108; Kd = 128;
                Xh = g_xdh;
                Wf = g_Wsf + (size_t)bn0 * 128;
            }
        } else {
            tap = c >> 1; cc = c & 1; Kd = 128;
            Xh = g_hdh;
            Wf = g_W1f + ((size_t)tap * 256 + bn0) * 128;
        }
        const uint32_t S = sb + (c % NSTG) * STG;
        const int row = tid >> 1;
        int gi = ridx[tap * 128 + row];
        unsigned sz = (gi >= 0) ? 16u : 0u;
        size_t xo = (size_t)(gi >= 0 ? gi : 0) * Kd + cc * 64;
        size_t woff = (size_t)row * Kd + cc * 64;
#pragma unroll
        for (int i = 0; i < 4; ++i) {
            int seg = (tid & 1) * 4 + i;
            uint32_t off = SWZ(row * 128 + seg * 16);
            cpa(S + off,         Xh + xo + seg * 8, sz);
            cpa(S + 16384 + off, Wf + woff + seg * 8, 16u);
        }
    };

    issue(0); cp_commit();
    issue(1); cp_commit();

    for (int c = 0; c < NC; ++c) {
        cp_wait1();          // stage c complete (<=1 group pending)
        __syncthreads();     // all threads' stage-c data visible; stage c-1 free

        const uint32_t Sb = sb + (c % NSTG) * STG;
#pragma unroll
        for (int ks = 0; ks < 4; ++ks) {
            uint32_t a[2][4], b[4][4];
#pragma unroll
            for (int mt = 0; mt < 2; ++mt)
                ldsm4(Sb + arow[mt] * 128 +
                      ((ks * 32 + akb) ^ ((arow[mt] & 7) * 16)), a[mt]);
#pragma unroll
            for (int p = 0; p < 4; ++p)
                ldsm4(Sb + 16384 + brow[p] * 128 +
                      ((ks * 32 + bkb) ^ ((brow[p] & 7) * 16)), b[p]);
#pragma unroll
            for (int mt = 0; mt < 2; ++mt)
#pragma unroll
                for (int nt = 0; nt < 8; ++nt)
                    mma16816(acc[mt][nt], a[mt],
                             b[nt >> 1][(nt & 1) * 2], b[nt >> 1][(nt & 1) * 2 + 1]);
        }
        if (c + 2 < NC) issue(c + 2);
        cp_commit();
    }

    // epilogue: registers -> gmem with fused bias
#pragma unroll
    for (int nt = 0; nt < 8; ++nt) {
        int col = bn0 + nbase + nt * 8 + (lane & 3) * 2;
        float bx = bias[col]     + (SECOND ? bsk[col]     : 0.f);
        float by = bias[col + 1] + (SECOND ? bsk[col + 1] : 0.f);
#pragma unroll
        for (int mt = 0; mt < 2; ++mt) {
            int r0 = bm0 + mbase + mt * 16 + (lane >> 2);
            if (r0 < M) {
                float2 v = make_float2(acc[mt][nt][0] + bx, acc[mt][nt][1] + by);
                *(float2*)(out + (size_t)r0 * 256 + col) = v;
            }
            int r1 = r0 + 8;
            if (r1 < M) {
                float2 v = make_float2(acc[mt][nt][2] + bx, acc[mt][nt][3] + by);
                *(float2*)(out + (size_t)r1 * 256 + col) = v;
            }
        }
    }
}

// ---------------- launch ----------------
extern "C" void kernel_launch(void* const* d_in, const int* in_sizes, int n_in,
                              void* d_out, int out_size) {
    const float* feats = (const float*)d_in[0];
    const float* gn1w  = (const float*)d_in[1];
    const float* gn1b  = (const float*)d_in[2];
    const float* W1    = (const float*)d_in[3];
    const float* b1    = (const float*)d_in[4];
    const float* gn2w  = (const float*)d_in[5];
    const float* gn2b  = (const float*)d_in[6];
    const float* W2    = (const float*)d_in[7];
    const float* b2    = (const float*)d_in[8];
    const float* Wsk   = (const float*)d_in[9];
    const float* bsk   = (const float*)d_in[10];
    const int*   seg   = (const int*)d_in[11];
    const int*   nbr   = (const int*)d_in[12];

    const int N = in_sizes[0] / 128;
    const int M = in_sizes[12] / 27;

    cudaFuncSetAttribute(k_conv_mma<false>,
                         cudaFuncAttributeMaxDynamicSharedMemorySize, SMEM_SZ);
    cudaFuncSetAttribute(k_conv_mma<true>,
                         cudaFuncAttributeMaxDynamicSharedMemorySize, SMEM_SZ);

    // weight preprocessing (transpose + fp16 round)
    k_wsplit<0><<<(27 * 256 * 128 + 255) / 256, 256>>>(W1, 128, 256, 27 * 256 * 128);
    k_wsplit<1><<<(27 * 256 * 256 + 255) / 256, 256>>>(W2, 256, 256, 27 * 256 * 256);
    k_wsplit<2><<<(256 * 128 + 255) / 256, 256>>>(Wsk, 128, 256, 256 * 128);

    // pooling accumulators
    k_zero<<<(M * 32 + 255) / 256, 256>>>(M);
    // GroupNorm-1 stats
    k_gn_partial<128, false><<<NPART, 128>>>(feats, N);
    k_gn_reduce<<<1, 64>>>(1.f / (4.f * (float)N), 0);
    // silu(gn1(x)) + pooling
    k_act_pool<<<N, 128>>>(feats, gn1w, gn1b, seg);
    // means -> fp16
    k_finalize<<<(M * 128 + 255) / 256, 256>>>(M);
    // conv1 (HMMA fp16 single-pass)
    const int gm = (M + 127) >> 7;
    k_conv_mma<false><<<dim3(2, gm), 256, SMEM_SZ>>>(nbr, b1, nullptr, nullptr, M);
    // GroupNorm-2 stats
    k_gn_partial<256, true><<<NPART, 256>>>(nullptr, M);
    k_gn_reduce<<<1, 64>>>(1.f / (8.f * (float)M), 1);
    // h2 = silu(gn2(h1)) -> fp16
    k_act2<<<(M * 256 + 255) / 256, 256>>>(gn2w, gn2b, M);
    // conv2 + fused skip (HMMA fp16 single-pass) -> d_out
    k_conv_mma<true><<<dim3(2, gm), 256, SMEM_SZ>>>(nbr, b2, bsk, (float*)d_out, M);
}